// round 1
// baseline (speedup 1.0000x reference)
#include <cuda_runtime.h>
#include <cuda_bf16.h>

// Problem constants (fixed shapes for GNNNet_678604833376)
constexpr int B  = 2;
constexpr int N  = 50000;
constexpr int D  = 128;
constexpr int E  = 640000;
constexpr int E2 = E + N;          // edges + self loops
constexpr int M  = B * N;          // flattened GEMM rows

// ---------------------------------------------------------------------------
// Scratch (static device allocations — no cudaMalloc allowed)
// ---------------------------------------------------------------------------
__device__ float g_deg[N];
__device__ float g_dinv[N];
__device__ int   g_counts[N];
__device__ int   g_offsets[N + 1];
__device__ int   g_cursor[N];
__device__ int   g_sorted[E2];
__device__ float g_h[(size_t)B * N * D];   // GEMM output / aggregate input
__device__ float g_t[(size_t)B * N * D];   // layer-1 activation

// ---------------------------------------------------------------------------
// Preprocessing kernels
// ---------------------------------------------------------------------------
__global__ void k_init() {
    int i = blockIdx.x * blockDim.x + threadIdx.x;
    if (i < N) { g_deg[i] = 1.0f; g_counts[i] = 0; }   // self-loop weight 1
}

__global__ void k_accum(const int* __restrict__ col, const float* __restrict__ ea) {
    int e = blockIdx.x * blockDim.x + threadIdx.x;
    if (e < E) {
        int c = col[e];
        atomicAdd(&g_deg[c], ea[e]);
        atomicAdd(&g_counts[c], 1);
    }
}

__global__ void k_dinv() {
    int i = blockIdx.x * blockDim.x + threadIdx.x;
    if (i < N) g_dinv[i] = rsqrtf(g_deg[i]);   // deg >= 1 always (self loop)
}

// Single-block exclusive scan of (counts[i] + 1) -> offsets, cursor
__global__ void k_scan() {
    __shared__ int s[1024];
    const int t = threadIdx.x;
    const int chunk = (N + 1023) / 1024;       // 49
    int b0 = t * chunk;
    int e0 = min(b0 + chunk, N);
    int sum = 0;
    for (int i = b0; i < e0; ++i) sum += g_counts[i] + 1;
    s[t] = sum;
    __syncthreads();
    for (int d = 1; d < 1024; d <<= 1) {
        int other = (t >= d) ? s[t - d] : 0;
        __syncthreads();
        s[t] += other;
        __syncthreads();
    }
    int off = s[t] - sum;                       // exclusive prefix
    for (int i = b0; i < e0; ++i) {
        g_offsets[i] = off;
        g_cursor[i]  = off;
        off += g_counts[i] + 1;
    }
    if (t == 0) g_offsets[N] = E2;
}

__global__ void k_fill(const int* __restrict__ col) {
    int e = blockIdx.x * blockDim.x + threadIdx.x;
    if (e >= E2) return;
    int dst = (e < E) ? col[e] : (e - E);
    int pos = atomicAdd(&g_cursor[dst], 1);
    g_sorted[pos] = e;
}

// ---------------------------------------------------------------------------
// GEMM: Y[M,128] = X[M,128] @ W[128,128]   (fp32, smem-tiled, 4x8 microtile)
// blockDim = 256, 64-row tile per block.
// smem: W full (128*128) + X tile (64 rows, stride 132 to avoid conflicts)
// ---------------------------------------------------------------------------
constexpr int GEMM_SMEM = (128 * 128 + 64 * 132) * (int)sizeof(float);  // 99328 B

__global__ void k_gemm(const float* __restrict__ X, const float* __restrict__ W,
                       float* __restrict__ Y, int m) {
    extern __shared__ float sm[];
    float* Ws = sm;               // [128][128]
    float* Xs = sm + 128 * 128;   // [64][132]

    const int tid = threadIdx.x;

    // Load W (16384 floats = 4096 float4; 16 per thread)
    {
        const float4* Wg  = (const float4*)W;
        float4*       Wsv = (float4*)Ws;
#pragma unroll
        for (int i = 0; i < 16; ++i) Wsv[tid + i * 256] = Wg[tid + i * 256];
    }

    const int row0 = blockIdx.x * 64;

    // Load X tile (64 x 128 = 2048 float4; 8 per thread), zero-pad OOB rows
#pragma unroll
    for (int i = 0; i < 8; ++i) {
        int idx = tid + i * 256;        // 0..2047
        int r   = idx >> 5;
        int c4  = idx & 31;
        float4 v = make_float4(0.f, 0.f, 0.f, 0.f);
        if (row0 + r < m)
            v = ((const float4*)(X + (size_t)(row0 + r) * 128))[c4];
        *(float4*)(Xs + r * 132 + c4 * 4) = v;
    }
    __syncthreads();

    const int rg = (tid >> 4) * 4;     // row group: 0,4,...,60
    const int cg = (tid & 15) * 8;     // col group: 0,8,...,120

    float acc[4][8];
#pragma unroll
    for (int i = 0; i < 4; ++i)
#pragma unroll
        for (int j = 0; j < 8; ++j) acc[i][j] = 0.f;

#pragma unroll 4
    for (int k = 0; k < 128; ++k) {
        float a0 = Xs[(rg + 0) * 132 + k];
        float a1 = Xs[(rg + 1) * 132 + k];
        float a2 = Xs[(rg + 2) * 132 + k];
        float a3 = Xs[(rg + 3) * 132 + k];
        float4 t0 = *(const float4*)(Ws + k * 128 + cg);
        float4 t1 = *(const float4*)(Ws + k * 128 + cg + 4);
        float bb[8] = {t0.x, t0.y, t0.z, t0.w, t1.x, t1.y, t1.z, t1.w};
        float aa[4] = {a0, a1, a2, a3};
#pragma unroll
        for (int i = 0; i < 4; ++i)
#pragma unroll
            for (int j = 0; j < 8; ++j) acc[i][j] += aa[i] * bb[j];
    }

#pragma unroll
    for (int i = 0; i < 4; ++i) {
        int r = row0 + rg + i;
        if (r < m) {
            float4 o0 = make_float4(acc[i][0], acc[i][1], acc[i][2], acc[i][3]);
            float4 o1 = make_float4(acc[i][4], acc[i][5], acc[i][6], acc[i][7]);
            *(float4*)(Y + (size_t)r * 128 + cg)     = o0;
            *(float4*)(Y + (size_t)r * 128 + cg + 4) = o1;
        }
    }
}

// ---------------------------------------------------------------------------
// Aggregation: one warp per destination node; lane = 4-column slice (float4).
// Both batches handled in the same edge loop. out = relu(agg + bias).
// ---------------------------------------------------------------------------
__global__ void k_agg(const float* __restrict__ H,
                      const int* __restrict__ rows,
                      const float* __restrict__ eattr,
                      const float* __restrict__ bias,
                      float* __restrict__ out) {
    int warp = (blockIdx.x * blockDim.x + threadIdx.x) >> 5;
    if (warp >= N) return;
    const int lane = threadIdx.x & 31;
    const int node = warp;

    const int s = g_offsets[node];
    const int e = g_offsets[node + 1];
    const float di = g_dinv[node];

    const float4* H0 = (const float4*)H;                       // batch 0
    const float4* H1 = (const float4*)(H + (size_t)N * 128);   // batch 1

    float4 acc0 = make_float4(0.f, 0.f, 0.f, 0.f);
    float4 acc1 = make_float4(0.f, 0.f, 0.f, 0.f);

    for (int p = s; p < e; ++p) {
        int eid = g_sorted[p];
        int src; float w;
        if (eid < E) { src = rows[eid]; w = eattr[eid]; }
        else         { src = eid - E;   w = 1.0f; }
        float nrm = g_dinv[src] * w * di;
        float4 v0 = H0[src * 32 + lane];
        float4 v1 = H1[src * 32 + lane];
        acc0.x += v0.x * nrm; acc0.y += v0.y * nrm;
        acc0.z += v0.z * nrm; acc0.w += v0.w * nrm;
        acc1.x += v1.x * nrm; acc1.y += v1.y * nrm;
        acc1.z += v1.z * nrm; acc1.w += v1.w * nrm;
    }

    float4 bb = ((const float4*)bias)[lane];
    float4 o0 = make_float4(fmaxf(acc0.x + bb.x, 0.f), fmaxf(acc0.y + bb.y, 0.f),
                            fmaxf(acc0.z + bb.z, 0.f), fmaxf(acc0.w + bb.w, 0.f));
    float4 o1 = make_float4(fmaxf(acc1.x + bb.x, 0.f), fmaxf(acc1.y + bb.y, 0.f),
                            fmaxf(acc1.z + bb.z, 0.f), fmaxf(acc1.w + bb.w, 0.f));

    float4* O0 = (float4*)out;
    float4* O1 = (float4*)(out + (size_t)N * 128);
    O0[node * 32 + lane] = o0;
    O1[node * 32 + lane] = o1;
}

// ---------------------------------------------------------------------------
// Launch
// ---------------------------------------------------------------------------
extern "C" void kernel_launch(void* const* d_in, const int* in_sizes, int n_in,
                              void* d_out, int out_size) {
    const float* x   = (const float*)d_in[0];
    const int*   eix = (const int*)  d_in[1];
    const float* ea  = (const float*)d_in[2];
    const float* W1  = (const float*)d_in[3];
    const float* b1  = (const float*)d_in[4];
    const float* W2  = (const float*)d_in[5];
    const float* b2  = (const float*)d_in[6];
    float* out = (float*)d_out;

    const int* rowp = eix;       // edge_index[0]
    const int* colp = eix + E;   // edge_index[1]

    float *hbuf = nullptr, *tbuf = nullptr;
    cudaGetSymbolAddress((void**)&hbuf, g_h);
    cudaGetSymbolAddress((void**)&tbuf, g_t);

    cudaFuncSetAttribute(k_gemm, cudaFuncAttributeMaxDynamicSharedMemorySize,
                         GEMM_SMEM);

    // Preprocess: degrees, rsqrt norm, CSR-by-destination
    k_init <<<(N + 255) / 256, 256>>>();
    k_accum<<<(E + 255) / 256, 256>>>(colp, ea);
    k_dinv <<<(N + 255) / 256, 256>>>();
    k_scan <<<1, 1024>>>();
    k_fill <<<(E2 + 255) / 256, 256>>>(colp);

    const int gemm_blocks = (M + 63) / 64;
    const int agg_blocks  = (N + 7) / 8;        // 8 warps / block

    // Layer 1: h = x @ W1 ; t = relu(agg(h) + b1)
    k_gemm<<<gemm_blocks, 256, GEMM_SMEM>>>(x, W1, hbuf, M);
    k_agg <<<agg_blocks, 256>>>(hbuf, rowp, ea, b1, tbuf);

    // Layer 2: h = t @ W2 ; out = relu(agg(h) + b2)
    k_gemm<<<gemm_blocks, 256, GEMM_SMEM>>>(tbuf, W2, hbuf, M);
    k_agg <<<agg_blocks, 256>>>(hbuf, rowp, ea, b2, out);
}

// round 2
// speedup vs baseline: 1.2186x; 1.2186x over previous
#include <cuda_runtime.h>
#include <cuda_bf16.h>

// Problem constants (fixed shapes for GNNNet_678604833376)
constexpr int B  = 2;
constexpr int N  = 50000;
constexpr int D  = 128;
constexpr int E  = 640000;
constexpr int E2 = E + N;          // edges + self loops
constexpr int M  = B * N;          // flattened GEMM rows
constexpr int NBLK = (N + 1023) / 1024;   // 49 scan blocks

// ---------------------------------------------------------------------------
// Scratch (static device allocations — no cudaMalloc allowed)
// ---------------------------------------------------------------------------
__device__ float g_deg[N];
__device__ float g_dinv[N];
__device__ int   g_counts[N];
__device__ int   g_offsets[N + 1];
__device__ int   g_cursor[N];
__device__ int   g_bsum[64];
__device__ int   g_boff[64];
__device__ int   g_sorted[E2];
__device__ float g_h[(size_t)B * N * D];   // GEMM output / aggregate input
__device__ float g_t[(size_t)B * N * D];   // layer-1 activation

// ---------------------------------------------------------------------------
// Packed fp32x2 helpers (Blackwell FFMA2 — only reachable via PTX)
// ---------------------------------------------------------------------------
__device__ __forceinline__ unsigned long long ffma2(unsigned long long a,
                                                    unsigned long long b,
                                                    unsigned long long c) {
    unsigned long long d;
    asm("fma.rn.f32x2 %0, %1, %2, %3;" : "=l"(d) : "l"(a), "l"(b), "l"(c));
    return d;
}
__device__ __forceinline__ unsigned long long dup2(float a) {
    unsigned long long d;
    asm("mov.b64 %0, {%1, %1};" : "=l"(d) : "f"(a));
    return d;
}
__device__ __forceinline__ void unpack2(unsigned long long v, float& lo, float& hi) {
    asm("mov.b64 {%0, %1}, %2;" : "=f"(lo), "=f"(hi) : "l"(v));
}

// ---------------------------------------------------------------------------
// Preprocessing
// ---------------------------------------------------------------------------
__global__ void k_init() {
    int i = blockIdx.x * blockDim.x + threadIdx.x;
    if (i < N) { g_deg[i] = 1.0f; g_counts[i] = 0; }   // self-loop weight 1
}

__global__ void k_accum(const int* __restrict__ col, const float* __restrict__ ea) {
    int e = blockIdx.x * blockDim.x + threadIdx.x;
    if (e < E) {
        int c = col[e];
        atomicAdd(&g_deg[c], ea[e]);
        atomicAdd(&g_counts[c], 1);
    }
}

// Per-1024-block sum of (counts+1); also computes dinv (deg is final here).
__global__ void k_bsum() {
    __shared__ int ws[32];
    int i = blockIdx.x * 1024 + threadIdx.x;
    int v = 0;
    if (i < N) {
        v = g_counts[i] + 1;
        g_dinv[i] = rsqrtf(g_deg[i]);
    }
    // warp reduce
    int s = v;
    #pragma unroll
    for (int d = 16; d > 0; d >>= 1) s += __shfl_down_sync(0xffffffffu, s, d);
    if ((threadIdx.x & 31) == 0) ws[threadIdx.x >> 5] = s;
    __syncthreads();
    if (threadIdx.x < 32) {
        int t = ws[threadIdx.x];
        #pragma unroll
        for (int d = 16; d > 0; d >>= 1) t += __shfl_down_sync(0xffffffffu, t, d);
        if (threadIdx.x == 0) g_bsum[blockIdx.x] = t;
    }
}

// Exclusive scan of the 49 block sums (one 64-thread block).
__global__ void k_bscan() {
    __shared__ int s[64];
    int t = threadIdx.x;
    int v = (t < NBLK) ? g_bsum[t] : 0;
    s[t] = v;
    __syncthreads();
    #pragma unroll
    for (int d = 1; d < 64; d <<= 1) {
        int o = (t >= d) ? s[t - d] : 0;
        __syncthreads();
        s[t] += o;
        __syncthreads();
    }
    if (t < NBLK) g_boff[t] = s[t] - v;   // exclusive
}

// Per-block exclusive scan + base offset -> offsets, cursor.
__global__ void k_offsets() {
    __shared__ int s[1024];
    int t = threadIdx.x;
    int i = blockIdx.x * 1024 + t;
    int v = (i < N) ? g_counts[i] + 1 : 0;
    s[t] = v;
    __syncthreads();
    #pragma unroll
    for (int d = 1; d < 1024; d <<= 1) {
        int o = (t >= d) ? s[t - d] : 0;
        __syncthreads();
        s[t] += o;
        __syncthreads();
    }
    if (i < N) {
        int off = g_boff[blockIdx.x] + s[t] - v;
        g_offsets[i] = off;
        g_cursor[i]  = off;
    }
    if (i == 0) g_offsets[N] = E2;
}

__global__ void k_fill(const int* __restrict__ col) {
    int e = blockIdx.x * blockDim.x + threadIdx.x;
    if (e >= E2) return;
    int dst = (e < E) ? col[e] : (e - E);
    int pos = atomicAdd(&g_cursor[dst], 1);
    g_sorted[pos] = e;
}

// ---------------------------------------------------------------------------
// GEMM: Y[M,128] = X[M,128] @ W[128,128]  (fp32, FFMA2 packed pairs)
// blockDim = 256, 64-row tile per block, 4x8 microtile per thread.
// ---------------------------------------------------------------------------
constexpr int GEMM_SMEM = (128 * 128 + 64 * 132) * (int)sizeof(float);  // 99328 B

__global__ void k_gemm(const float* __restrict__ X, const float* __restrict__ W,
                       float* __restrict__ Y, int m) {
    extern __shared__ float sm[];
    float* Ws = sm;               // [128][128]
    float* Xs = sm + 128 * 128;   // [64][132]

    const int tid = threadIdx.x;

    // Load W (4096 float4; 16 per thread)
    {
        const float4* Wg  = (const float4*)W;
        float4*       Wsv = (float4*)Ws;
#pragma unroll
        for (int i = 0; i < 16; ++i) Wsv[tid + i * 256] = Wg[tid + i * 256];
    }

    const int row0 = blockIdx.x * 64;

    // Load X tile (2048 float4; 8 per thread), zero-pad OOB rows
#pragma unroll
    for (int i = 0; i < 8; ++i) {
        int idx = tid + i * 256;
        int r   = idx >> 5;
        int c4  = idx & 31;
        float4 v = make_float4(0.f, 0.f, 0.f, 0.f);
        if (row0 + r < m)
            v = ((const float4*)(X + (size_t)(row0 + r) * 128))[c4];
        *(float4*)(Xs + r * 132 + c4 * 4) = v;
    }
    __syncthreads();

    const int rg = (tid >> 4) * 4;     // row group: 0,4,...,60
    const int cg = (tid & 15) * 8;     // col group: 0,8,...,120

    // acc[i][p]: row i, column pair p (pair = 2 adjacent fp32 columns)
    unsigned long long acc[4][4];
#pragma unroll
    for (int i = 0; i < 4; ++i)
#pragma unroll
        for (int p = 0; p < 4; ++p) acc[i][p] = 0ull;

#pragma unroll 4
    for (int k = 0; k < 128; ++k) {
        // B pairs: 4 packed fp32x2 straight out of smem (two LDS.128)
        longlong2 bv0 = *(const longlong2*)(Ws + k * 128 + cg);
        longlong2 bv1 = *(const longlong2*)(Ws + k * 128 + cg + 4);
        unsigned long long b[4] = {(unsigned long long)bv0.x, (unsigned long long)bv0.y,
                                   (unsigned long long)bv1.x, (unsigned long long)bv1.y};
        unsigned long long a[4];
#pragma unroll
        for (int i = 0; i < 4; ++i) a[i] = dup2(Xs[(rg + i) * 132 + k]);
#pragma unroll
        for (int i = 0; i < 4; ++i)
#pragma unroll
            for (int p = 0; p < 4; ++p) acc[i][p] = ffma2(a[i], b[p], acc[i][p]);
    }

#pragma unroll
    for (int i = 0; i < 4; ++i) {
        int r = row0 + rg + i;
        if (r < m) {
            float o[8];
#pragma unroll
            for (int p = 0; p < 4; ++p) unpack2(acc[i][p], o[2 * p], o[2 * p + 1]);
            *(float4*)(Y + (size_t)r * 128 + cg)     = make_float4(o[0], o[1], o[2], o[3]);
            *(float4*)(Y + (size_t)r * 128 + cg + 4) = make_float4(o[4], o[5], o[6], o[7]);
        }
    }
}

// ---------------------------------------------------------------------------
// Aggregation: one warp per destination node; lane = 4-column slice (float4).
// ---------------------------------------------------------------------------
__global__ void k_agg(const float* __restrict__ H,
                      const int* __restrict__ rows,
                      const float* __restrict__ eattr,
                      const float* __restrict__ bias,
                      float* __restrict__ out) {
    int warp = (blockIdx.x * blockDim.x + threadIdx.x) >> 5;
    if (warp >= N) return;
    const int lane = threadIdx.x & 31;
    const int node = warp;

    const int s = g_offsets[node];
    const int e = g_offsets[node + 1];
    const float di = g_dinv[node];

    const float4* H0 = (const float4*)H;
    const float4* H1 = (const float4*)(H + (size_t)N * 128);

    float4 acc0 = make_float4(0.f, 0.f, 0.f, 0.f);
    float4 acc1 = make_float4(0.f, 0.f, 0.f, 0.f);

    for (int p = s; p < e; ++p) {
        int eid = g_sorted[p];
        int src; float w;
        if (eid < E) { src = rows[eid]; w = eattr[eid]; }
        else         { src = eid - E;   w = 1.0f; }
        float nrm = g_dinv[src] * w * di;
        float4 v0 = H0[src * 32 + lane];
        float4 v1 = H1[src * 32 + lane];
        acc0.x += v0.x * nrm; acc0.y += v0.y * nrm;
        acc0.z += v0.z * nrm; acc0.w += v0.w * nrm;
        acc1.x += v1.x * nrm; acc1.y += v1.y * nrm;
        acc1.z += v1.z * nrm; acc1.w += v1.w * nrm;
    }

    float4 bb = ((const float4*)bias)[lane];
    float4 o0 = make_float4(fmaxf(acc0.x + bb.x, 0.f), fmaxf(acc0.y + bb.y, 0.f),
                            fmaxf(acc0.z + bb.z, 0.f), fmaxf(acc0.w + bb.w, 0.f));
    float4 o1 = make_float4(fmaxf(acc1.x + bb.x, 0.f), fmaxf(acc1.y + bb.y, 0.f),
                            fmaxf(acc1.z + bb.z, 0.f), fmaxf(acc1.w + bb.w, 0.f));

    float4* O0 = (float4*)out;
    float4* O1 = (float4*)(out + (size_t)N * 128);
    O0[node * 32 + lane] = o0;
    O1[node * 32 + lane] = o1;
}

// ---------------------------------------------------------------------------
// Launch
// ---------------------------------------------------------------------------
extern "C" void kernel_launch(void* const* d_in, const int* in_sizes, int n_in,
                              void* d_out, int out_size) {
    const float* x   = (const float*)d_in[0];
    const int*   eix = (const int*)  d_in[1];
    const float* ea  = (const float*)d_in[2];
    const float* W1  = (const float*)d_in[3];
    const float* b1  = (const float*)d_in[4];
    const float* W2  = (const float*)d_in[5];
    const float* b2  = (const float*)d_in[6];
    float* out = (float*)d_out;

    const int* rowp = eix;       // edge_index[0]
    const int* colp = eix + E;   // edge_index[1]

    float *hbuf = nullptr, *tbuf = nullptr;
    cudaGetSymbolAddress((void**)&hbuf, g_h);
    cudaGetSymbolAddress((void**)&tbuf, g_t);

    cudaFuncSetAttribute(k_gemm, cudaFuncAttributeMaxDynamicSharedMemorySize,
                         GEMM_SMEM);

    // Preprocess: degrees + CSR-by-destination (multi-block scan)
    k_init   <<<(N + 255) / 256, 256>>>();
    k_accum  <<<(E + 255) / 256, 256>>>(colp, ea);
    k_bsum   <<<NBLK, 1024>>>();
    k_bscan  <<<1, 64>>>();
    k_offsets<<<NBLK, 1024>>>();
    k_fill   <<<(E2 + 255) / 256, 256>>>(colp);

    const int gemm_blocks = (M + 63) / 64;
    const int agg_blocks  = (N + 7) / 8;        // 8 warps / block

    // Layer 1: h = x @ W1 ; t = relu(agg(h) + b1)
    k_gemm<<<gemm_blocks, 256, GEMM_SMEM>>>(x, W1, hbuf, M);
    k_agg <<<agg_blocks, 256>>>(hbuf, rowp, ea, b1, tbuf);

    // Layer 2: h = t @ W2 ; out = relu(agg(h) + b2)
    k_gemm<<<gemm_blocks, 256, GEMM_SMEM>>>(tbuf, W2, hbuf, M);
    k_agg <<<agg_blocks, 256>>>(hbuf, rowp, ea, b2, out);
}

// round 3
// speedup vs baseline: 2.0849x; 1.7109x over previous
#include <cuda_runtime.h>
#include <cuda_fp16.h>

// Problem constants (fixed shapes for GNNNet_678604833376)
constexpr int B  = 2;
constexpr int N  = 50000;
constexpr int D  = 128;
constexpr int E  = 640000;
constexpr int E2 = E + N;          // edges + self loops
constexpr int M  = B * N;          // flattened GEMM rows
constexpr int NBLK = (N + 1023) / 1024;   // 49 scan blocks

// ---------------------------------------------------------------------------
// Scratch (static device allocations — no cudaMalloc allowed)
// ---------------------------------------------------------------------------
__device__ float g_deg[N];
__device__ float g_dinv[N];
__device__ int   g_counts[N];
__device__ int   g_offsets[N + 1];
__device__ int   g_cursor[N];
__device__ int   g_bsum[64];
__device__ int   g_sorted[E2];
__device__ float g_h[(size_t)B * N * D];   // GEMM output / aggregate input
__device__ float g_t[(size_t)B * N * D];   // layer-1 activation
// Pre-split, pre-transposed weights: [which][n*128+k], W_T[n][k] = W[k][n]
__device__ __align__(16) __half g_W_hi[2][D * D];
__device__ __align__(16) __half g_W_lo[2][D * D];

// ---------------------------------------------------------------------------
// Weight prep: fp32 -> (hi, lo) fp16 split, transposed to n-major
// ---------------------------------------------------------------------------
__global__ void k_wprep(const float* __restrict__ W1, const float* __restrict__ W2) {
    int idx = blockIdx.x * blockDim.x + threadIdx.x;   // 0 .. 2*16384
    if (idx >= 2 * D * D) return;
    int sel = idx >> 14;
    int r   = idx & (D * D - 1);
    int k   = r >> 7;
    int n   = r & 127;
    float w = (sel == 0) ? W1[k * D + n] : W2[k * D + n];
    __half hi = __float2half_rn(w);
    __half lo = __float2half_rn(w - __half2float(hi));
    g_W_hi[sel][n * D + k] = hi;
    g_W_lo[sel][n * D + k] = lo;
}

// ---------------------------------------------------------------------------
// Preprocessing
// ---------------------------------------------------------------------------
__global__ void k_init() {
    int i = blockIdx.x * blockDim.x + threadIdx.x;
    if (i < N) { g_deg[i] = 1.0f; g_counts[i] = 0; }   // self-loop weight 1
}

__global__ void k_accum(const int* __restrict__ col, const float* __restrict__ ea) {
    int e = blockIdx.x * blockDim.x + threadIdx.x;
    if (e < E) {
        int c = col[e];
        atomicAdd(&g_deg[c], ea[e]);
        atomicAdd(&g_counts[c], 1);
    }
}

// Per-1024-block sum of (counts+1); also computes dinv (deg is final here).
__global__ void k_bsum() {
    __shared__ int ws[32];
    int i = blockIdx.x * 1024 + threadIdx.x;
    int v = 0;
    if (i < N) {
        v = g_counts[i] + 1;
        g_dinv[i] = rsqrtf(g_deg[i]);
    }
    int s = v;
    #pragma unroll
    for (int d = 16; d > 0; d >>= 1) s += __shfl_down_sync(0xffffffffu, s, d);
    if ((threadIdx.x & 31) == 0) ws[threadIdx.x >> 5] = s;
    __syncthreads();
    if (threadIdx.x < 32) {
        int t = ws[threadIdx.x];
        #pragma unroll
        for (int d = 16; d > 0; d >>= 1) t += __shfl_down_sync(0xffffffffu, t, d);
        if (threadIdx.x == 0) g_bsum[blockIdx.x] = t;
    }
}

// Per-block exclusive scan + cross-block base (serial sum over <=49 entries).
__global__ void k_offsets() {
    __shared__ int s[1024];
    __shared__ int sbase;
    int t = threadIdx.x;
    if (t == 0) {
        int b = 0;
        for (int j = 0; j < blockIdx.x; ++j) b += g_bsum[j];
        sbase = b;
    }
    int i = blockIdx.x * 1024 + t;
    int v = (i < N) ? g_counts[i] + 1 : 0;
    s[t] = v;
    __syncthreads();
    #pragma unroll
    for (int d = 1; d < 1024; d <<= 1) {
        int o = (t >= d) ? s[t - d] : 0;
        __syncthreads();
        s[t] += o;
        __syncthreads();
    }
    if (i < N) {
        int off = sbase + s[t] - v;
        g_offsets[i] = off;
        g_cursor[i]  = off;
    }
    if (i == 0) g_offsets[N] = E2;
}

__global__ void k_fill(const int* __restrict__ col) {
    int e = blockIdx.x * blockDim.x + threadIdx.x;
    if (e >= E2) return;
    int dst = (e < E) ? col[e] : (e - E);
    int pos = atomicAdd(&g_cursor[dst], 1);
    g_sorted[pos] = e;
}

// ---------------------------------------------------------------------------
// Tensor-core GEMM: Y[M,128] = X[M,128] @ W[128,128]
// Split-fp16 (Markidis): W,X -> hi+lo fp16; Y = Xh*Wh + Xh*Wl + Xl*Wh,
// fp32 accumulators -> near-fp32 accuracy. mma.sync.m16n8k16.
// Block: 64 rows x 128 cols, 256 threads (8 warps), warp tile 32x32.
// smem row stride 136 halves -> all fragment LDS are conflict-free.
// ---------------------------------------------------------------------------
constexpr int XS  = 136;                  // smem row stride in halves
constexpr int SW_HALVES = D * XS;         // 17408 per W copy
constexpr int SX_HALVES = 64 * XS;        // 8704 per X copy
constexpr int GEMM_SMEM = (2 * SW_HALVES + 2 * SX_HALVES) * 2;  // 104448 B

__device__ __forceinline__ void mma16816(float& c0, float& c1, float& c2, float& c3,
                                         unsigned a0, unsigned a1, unsigned a2, unsigned a3,
                                         unsigned b0, unsigned b1) {
    asm volatile("mma.sync.aligned.m16n8k16.row.col.f32.f16.f16.f32 "
                 "{%0,%1,%2,%3}, {%4,%5,%6,%7}, {%8,%9}, {%0,%1,%2,%3};"
                 : "+f"(c0), "+f"(c1), "+f"(c2), "+f"(c3)
                 : "r"(a0), "r"(a1), "r"(a2), "r"(a3), "r"(b0), "r"(b1));
}

__global__ void k_gemm(const float* __restrict__ X,
                       const __half* __restrict__ Whi, const __half* __restrict__ Wlo,
                       float* __restrict__ Y, int m) {
    extern __shared__ __half sm[];
    __half* sWh = sm;                         // [128][136]
    __half* sWl = sWh + SW_HALVES;
    __half* sXh = sWl + SW_HALVES;            // [64][136]
    __half* sXl = sXh + SX_HALVES;

    const int tid  = threadIdx.x;
    const int lane = tid & 31;
    const int warp = tid >> 5;
    const int wr   = warp & 1;                // row group (0,1) -> 32 rows
    const int wc   = warp >> 1;               // col group (0..3) -> 32 cols

    // Copy W hi/lo (n-major in gmem) into smem, 16B chunks.
#pragma unroll
    for (int i = 0; i < 8; ++i) {
        int idx = tid + i * 256;              // 0..2047 chunks of 8 halves
        int n   = idx >> 4;
        int kv  = idx & 15;
        *(uint4*)(sWh + n * XS + kv * 8) = *(const uint4*)(Whi + n * D + kv * 8);
        *(uint4*)(sWl + n * XS + kv * 8) = *(const uint4*)(Wlo + n * D + kv * 8);
    }

    const int row0 = blockIdx.x * 64;

    // Load X tile, split to fp16 hi/lo in-flight.
#pragma unroll
    for (int i = 0; i < 8; ++i) {
        int idx = tid + i * 256;              // 0..2047 float4 chunks
        int r   = idx >> 5;
        int c4  = idx & 31;
        float4 v = make_float4(0.f, 0.f, 0.f, 0.f);
        if (row0 + r < m)
            v = ((const float4*)(X + (size_t)(row0 + r) * D))[c4];
        __half h0 = __float2half_rn(v.x), h1 = __float2half_rn(v.y);
        __half h2 = __float2half_rn(v.z), h3 = __float2half_rn(v.w);
        __half l0 = __float2half_rn(v.x - __half2float(h0));
        __half l1 = __float2half_rn(v.y - __half2float(h1));
        __half l2 = __float2half_rn(v.z - __half2float(h2));
        __half l3 = __float2half_rn(v.w - __half2float(h3));
        __half2* dh = (__half2*)(sXh + r * XS + c4 * 4);
        __half2* dl = (__half2*)(sXl + r * XS + c4 * 4);
        dh[0] = __halves2half2(h0, h1); dh[1] = __halves2half2(h2, h3);
        dl[0] = __halves2half2(l0, l1); dl[1] = __halves2half2(l2, l3);
    }
    __syncthreads();

    float acc[2][4][4];
#pragma unroll
    for (int mi = 0; mi < 2; ++mi)
#pragma unroll
        for (int ni = 0; ni < 4; ++ni)
#pragma unroll
            for (int j = 0; j < 4; ++j) acc[mi][ni][j] = 0.f;

    const int arow = wr * 32 + (lane >> 2);   // fragment row within tile
    const int acol = (lane & 3) * 2;          // fragment k within step
    const int bn   = wc * 32 + (lane >> 2);   // fragment n within tile

#pragma unroll
    for (int kk = 0; kk < 8; ++kk) {
        const int k0 = kk * 16;
        unsigned ah[2][4], al[2][4], bh[4][2], bl[4][2];
#pragma unroll
        for (int mi = 0; mi < 2; ++mi) {
            int r = arow + mi * 16;
            ah[mi][0] = *(const unsigned*)(sXh + r * XS + k0 + acol);
            ah[mi][1] = *(const unsigned*)(sXh + (r + 8) * XS + k0 + acol);
            ah[mi][2] = *(const unsigned*)(sXh + r * XS + k0 + 8 + acol);
            ah[mi][3] = *(const unsigned*)(sXh + (r + 8) * XS + k0 + 8 + acol);
            al[mi][0] = *(const unsigned*)(sXl + r * XS + k0 + acol);
            al[mi][1] = *(const unsigned*)(sXl + (r + 8) * XS + k0 + acol);
            al[mi][2] = *(const unsigned*)(sXl + r * XS + k0 + 8 + acol);
            al[mi][3] = *(const unsigned*)(sXl + (r + 8) * XS + k0 + 8 + acol);
        }
#pragma unroll
        for (int ni = 0; ni < 4; ++ni) {
            int n = bn + ni * 8;
            bh[ni][0] = *(const unsigned*)(sWh + n * XS + k0 + acol);
            bh[ni][1] = *(const unsigned*)(sWh + n * XS + k0 + 8 + acol);
            bl[ni][0] = *(const unsigned*)(sWl + n * XS + k0 + acol);
            bl[ni][1] = *(const unsigned*)(sWl + n * XS + k0 + 8 + acol);
        }
#pragma unroll
        for (int mi = 0; mi < 2; ++mi)
#pragma unroll
            for (int ni = 0; ni < 4; ++ni) {
                float* c = acc[mi][ni];
                mma16816(c[0], c[1], c[2], c[3],
                         ah[mi][0], ah[mi][1], ah[mi][2], ah[mi][3],
                         bh[ni][0], bh[ni][1]);
                mma16816(c[0], c[1], c[2], c[3],
                         ah[mi][0], ah[mi][1], ah[mi][2], ah[mi][3],
                         bl[ni][0], bl[ni][1]);
                mma16816(c[0], c[1], c[2], c[3],
                         al[mi][0], al[mi][1], al[mi][2], al[mi][3],
                         bh[ni][0], bh[ni][1]);
            }
    }

    // Store: c0,c1 -> (r, col..col+1); c2,c3 -> (r+8, col..col+1)
#pragma unroll
    for (int mi = 0; mi < 2; ++mi) {
        int r = row0 + wr * 32 + mi * 16 + (lane >> 2);
#pragma unroll
        for (int ni = 0; ni < 4; ++ni) {
            int c = wc * 32 + ni * 8 + (lane & 3) * 2;
            if (r < m)
                *(float2*)(Y + (size_t)r * D + c) =
                    make_float2(acc[mi][ni][0], acc[mi][ni][1]);
            if (r + 8 < m)
                *(float2*)(Y + (size_t)(r + 8) * D + c) =
                    make_float2(acc[mi][ni][2], acc[mi][ni][3]);
        }
    }
}

// ---------------------------------------------------------------------------
// Aggregation: one warp per destination node; lane = 4-column slice (float4).
// ---------------------------------------------------------------------------
__global__ void k_agg(const float* __restrict__ H,
                      const int* __restrict__ rows,
                      const float* __restrict__ eattr,
                      const float* __restrict__ bias,
                      float* __restrict__ out) {
    int warp = (blockIdx.x * blockDim.x + threadIdx.x) >> 5;
    if (warp >= N) return;
    const int lane = threadIdx.x & 31;
    const int node = warp;

    const int s = g_offsets[node];
    const int e = g_offsets[node + 1];
    const float di = g_dinv[node];

    const float4* H0 = (const float4*)H;
    const float4* H1 = (const float4*)(H + (size_t)N * 128);

    float4 acc0 = make_float4(0.f, 0.f, 0.f, 0.f);
    float4 acc1 = make_float4(0.f, 0.f, 0.f, 0.f);

    for (int p = s; p < e; ++p) {
        int eid = g_sorted[p];
        int src; float w;
        if (eid < E) { src = rows[eid]; w = eattr[eid]; }
        else         { src = eid - E;   w = 1.0f; }
        float nrm = g_dinv[src] * w * di;
        float4 v0 = H0[src * 32 + lane];
        float4 v1 = H1[src * 32 + lane];
        acc0.x += v0.x * nrm; acc0.y += v0.y * nrm;
        acc0.z += v0.z * nrm; acc0.w += v0.w * nrm;
        acc1.x += v1.x * nrm; acc1.y += v1.y * nrm;
        acc1.z += v1.z * nrm; acc1.w += v1.w * nrm;
    }

    float4 bb = ((const float4*)bias)[lane];
    float4 o0 = make_float4(fmaxf(acc0.x + bb.x, 0.f), fmaxf(acc0.y + bb.y, 0.f),
                            fmaxf(acc0.z + bb.z, 0.f), fmaxf(acc0.w + bb.w, 0.f));
    float4 o1 = make_float4(fmaxf(acc1.x + bb.x, 0.f), fmaxf(acc1.y + bb.y, 0.f),
                            fmaxf(acc1.z + bb.z, 0.f), fmaxf(acc1.w + bb.w, 0.f));

    float4* O0 = (float4*)out;
    float4* O1 = (float4*)(out + (size_t)N * 128);
    O0[node * 32 + lane] = o0;
    O1[node * 32 + lane] = o1;
}

// ---------------------------------------------------------------------------
// Launch
// ---------------------------------------------------------------------------
extern "C" void kernel_launch(void* const* d_in, const int* in_sizes, int n_in,
                              void* d_out, int out_size) {
    const float* x   = (const float*)d_in[0];
    const int*   eix = (const int*)  d_in[1];
    const float* ea  = (const float*)d_in[2];
    const float* W1  = (const float*)d_in[3];
    const float* b1  = (const float*)d_in[4];
    const float* W2  = (const float*)d_in[5];
    const float* b2  = (const float*)d_in[6];
    float* out = (float*)d_out;

    const int* rowp = eix;       // edge_index[0]
    const int* colp = eix + E;   // edge_index[1]

    float *hbuf = nullptr, *tbuf = nullptr;
    __half *wh = nullptr, *wl = nullptr;
    cudaGetSymbolAddress((void**)&hbuf, g_h);
    cudaGetSymbolAddress((void**)&tbuf, g_t);
    cudaGetSymbolAddress((void**)&wh, g_W_hi);
    cudaGetSymbolAddress((void**)&wl, g_W_lo);

    cudaFuncSetAttribute(k_gemm, cudaFuncAttributeMaxDynamicSharedMemorySize,
                         GEMM_SMEM);

    const int gemm_blocks = (M + 63) / 64;
    const int agg_blocks  = (N + 7) / 8;        // 8 warps / block

    // Order chosen so the 4th launch is k_gemm (ncu -s window captures it).
    k_wprep  <<<(2 * D * D + 255) / 256, 256>>>(W1, W2);
    k_init   <<<(N + 255) / 256, 256>>>();
    k_accum  <<<(E + 255) / 256, 256>>>(colp, ea);

    // Layer 1 GEMM: h = x @ W1   (independent of CSR build)
    k_gemm<<<gemm_blocks, 256, GEMM_SMEM>>>(x, wh, wl, hbuf, M);

    // CSR build
    k_bsum   <<<NBLK, 1024>>>();
    k_offsets<<<NBLK, 1024>>>();
    k_fill   <<<(E2 + 255) / 256, 256>>>(colp);

    // Layer 1 aggregate: t = relu(agg(h) + b1)
    k_agg <<<agg_blocks, 256>>>(hbuf, rowp, ea, b1, tbuf);

    // Layer 2: h = t @ W2 ; out = relu(agg(h) + b2)
    k_gemm<<<gemm_blocks, 256, GEMM_SMEM>>>(tbuf, wh + D * D, wl + D * D, hbuf, M);
    k_agg <<<agg_blocks, 256>>>(hbuf, rowp, ea, b2, out);
}